// round 15
// baseline (speedup 1.0000x reference)
#include <cuda_runtime.h>
#include <cuda_fp16.h>
#include <math_constants.h>
#include <cstdint>

// Problem constants
#define BB    8
#define HQ    32
#define TQn   128
#define DD    128
#define HKV   8
#define MAXB  64
#define BSZ   128
#define NBL   32
#define REP   4
#define SCALE 0.08838834764831845f   // 128^-0.5
#define LOG2E 1.4426950408889634f

#define NTHREADS 128       // 4 warps, 64 q-rows per CTA
#define RSB   272          // smem row stride in BYTES (128 fp16 = 256B + 16B pad)

#define CHUNK_T 4          // kv tiles (of 128) per work chunk
#define NSLOTS 4096        // rowTile(8) * chunk(8) * hkv(8) * b(8)
#define NITEMS 512         // rowTile(8) * hkv(8) * b(8)
#define GRID1  304         // 2 CTAs per SM on 152 SMs

// smem byte offsets
#define T_QHI 0            // 64 x 272
#define T_QLO 17408
#define T_K   34816        // 128 x 272
#define T_V   69632
#define SMEM_BYTES 104448

// ---- global scratch ----
__device__ float        g_partO[NSLOTS][64 * DD];    // 134 MB unnormalized partial O
__device__ float        g_partDen[NSLOTS][64];
__device__ unsigned int g_itemCnt[NITEMS];
__device__ unsigned int g_ctr;
__device__ unsigned int g_exit;

// ---------------- PTX helpers ----------------
__device__ __forceinline__ uint32_t smem_u32(const void* p) {
    uint32_t a;
    asm("{ .reg .u64 t; cvta.to.shared.u64 t, %1; cvt.u32.u64 %0, t; }" : "=r"(a) : "l"(p));
    return a;
}
__device__ __forceinline__ float ex2f(float x) {
    float r; asm("ex2.approx.ftz.f32 %0, %1;" : "=f"(r) : "f"(x)); return r;
}
__device__ __forceinline__ uint32_t h2bits(__half2 h) {
    return *reinterpret_cast<uint32_t*>(&h);
}

#define LDSM4(r0, r1, r2, r3, addr) \
    asm volatile("ldmatrix.sync.aligned.m8n8.x4.shared.b16 {%0,%1,%2,%3},[%4];" \
        : "=r"(r0), "=r"(r1), "=r"(r2), "=r"(r3) : "r"(addr))
#define LDSM4T(r0, r1, r2, r3, addr) \
    asm volatile("ldmatrix.sync.aligned.m8n8.x4.trans.shared.b16 {%0,%1,%2,%3},[%4];" \
        : "=r"(r0), "=r"(r1), "=r"(r2), "=r"(r3) : "r"(addr))

__device__ __forceinline__ void mma16816(float* d, const uint32_t* a, uint32_t b0, uint32_t b1) {
    asm volatile("mma.sync.aligned.m16n8k16.row.col.f32.f16.f16.f32 "
        "{%0,%1,%2,%3},{%4,%5,%6,%7},{%8,%9},{%0,%1,%2,%3};"
        : "+f"(d[0]), "+f"(d[1]), "+f"(d[2]), "+f"(d[3])
        : "r"(a[0]), "r"(a[1]), "r"(a[2]), "r"(a[3]), "r"(b0), "r"(b1));
}

// fp32x4 -> single fp16x4
__device__ __forceinline__ uint2 pack4h(float4 v) {
    return make_uint2(h2bits(__floats2half2_rn(v.x, v.y)),
                      h2bits(__floats2half2_rn(v.z, v.w)));
}
// fp32x4 -> (hi fp16x4, lo fp16x4)
__device__ __forceinline__ void hilo4h(float4 v, uint2& hi2, uint2& lo2) {
    __half2 a = __floats2half2_rn(v.x, v.y);
    __half2 b = __floats2half2_rn(v.z, v.w);
    hi2 = make_uint2(h2bits(a), h2bits(b));
    lo2 = make_uint2(h2bits(__floats2half2_rn(v.x - __low2float(a), v.y - __high2float(a))),
                     h2bits(__floats2half2_rn(v.z - __low2float(b), v.w - __high2float(b))));
}

// ===================== fused stage: partial attention + last-CTA fixup =====================
__global__ __launch_bounds__(NTHREADS, 2)
void attn_fused(const float* __restrict__ q,
                const float* __restrict__ sk,
                const float* __restrict__ sv,
                const int*   __restrict__ bt,
                const int*   __restrict__ ctx,
                float*       __restrict__ out)
{
    const int tid  = threadIdx.x;
    const int wid  = tid >> 5;      // 0..3
    const int lane = tid & 31;

    extern __shared__ char smem[];
    const uint32_t sb = smem_u32(smem);
    __shared__ unsigned int s_idx;
    __shared__ int s_fix;

    const int wrow = wid * 16;
    const uint32_t qa_off = sb + T_QHI
        + (uint32_t)(wrow + (lane & 7) + ((lane >> 3) & 1) * 8) * RSB + ((lane >> 4) & 1) * 16;
    const uint32_t kb_off = sb + T_K
        + (uint32_t)((lane & 7) + ((lane >> 4) & 1) * 8) * RSB + ((lane >> 3) & 1) * 16;
    const uint32_t vb_off = sb + T_V
        + (uint32_t)((lane & 7) + ((lane >> 3) & 1) * 8) * RSB + ((lane >> 4) & 1) * 16;
    const uint32_t QLOD = (uint32_t)(T_QLO - T_QHI);

    while (true) {
        __syncthreads();                       // smem reuse safe across items
        if (tid == 0) s_idx = atomicAdd(&g_ctr, 1u);
        __syncthreads();
        const unsigned int idx = s_idx;
        if (idx >= NSLOTS) break;

        // decode: bits [2:0]=rowTile [5:3]=chunk [8:6]=hkv [11:9]=b
        const int rowTile = idx & 7;
        const int cchunk  = (idx >> 3) & 7;
        const int hkv     = (idx >> 6) & 7;
        const int b       = (idx >> 9) & 7;

        const int Lv = ctx[b];
        const int nT = (Lv + 127) >> 7;
        const int t0 = cchunk * CHUNK_T;
        if (t0 >= nT && cchunk != 0) continue;   // empty chunk (chunk0 always "runs")
        const int t1 = min(t0 + CHUNK_T, nT);
        const int nc_eff = max(1, (nT + CHUNK_T - 1) >> 2);

        const int hq    = hkv * REP + (rowTile >> 1);
        const int qrow0 = (rowTile & 1) * 64;
        const size_t outbase = ((size_t)(b * HQ + hq) * TQn + qrow0) * DD;

        // ---- load Q (scaled) -> smem hi/lo fp16 (64 rows) ----
        {
            const float4* qg = (const float4*)(q + outbase);
            #pragma unroll
            for (int it = 0; it < 16; it++) {
                int i2 = tid + it * NTHREADS;      // 0..2047
                int row = i2 >> 5, c4 = i2 & 31;
                float4 v = qg[i2];
                v.x *= SCALE; v.y *= SCALE; v.z *= SCALE; v.w *= SCALE;
                uint2 hi2, lo2;
                hilo4h(v, hi2, lo2);
                *(uint2*)(smem + T_QHI + row * RSB + c4 * 8) = hi2;
                *(uint2*)(smem + T_QLO + row * RSB + c4 * 8) = lo2;
            }
        }

        const float4* kb_g = (const float4*)(sk + (size_t)(b * HKV + hkv) * MAXB * BSZ * DD);
        const float4* vb_g = (const float4*)(sv + (size_t)(b * HKV + hkv) * MAXB * BSZ * DD);
        const int* btb = bt + b * NBL;

        float O[16][4];
        #pragma unroll
        for (int t = 0; t < 16; t++)
            #pragma unroll
            for (int j = 0; j < 4; j++) O[t][j] = 0.f;
        float denA = 0.f, denB = 0.f;

        for (int tile = t0; tile < t1; tile++) {
            const int phys = btb[tile];
            const int rem  = Lv - tile * 128;   // >0
            const float4* ks = kb_g + (size_t)phys * BSZ * 32;
            const float4* vs = vb_g + (size_t)phys * BSZ * 32;

            __syncthreads();
            #pragma unroll
            for (int it = 0; it < 32; it++) {
                int i2 = tid + it * NTHREADS;      // 0..4095
                int row = i2 >> 5, c4 = i2 & 31;
                bool valid = row < rem;
                float4 kv = valid ? ks[i2] : make_float4(0.f, 0.f, 0.f, 0.f);
                float4 vv = valid ? vs[i2] : make_float4(0.f, 0.f, 0.f, 0.f);
                *(uint2*)(smem + T_K + row * RSB + c4 * 8) = pack4h(kv);
                *(uint2*)(smem + T_V + row * RSB + c4 * 8) = pack4h(vv);
            }
            __syncthreads();

            // ---- QK: 2-term (qhi + qlo) x K ----
            float S[16][4];
            #pragma unroll
            for (int t = 0; t < 16; t++)
                #pragma unroll
                for (int j = 0; j < 4; j++) S[t][j] = 0.f;

            #pragma unroll
            for (int dc = 0; dc < 8; dc++) {
                uint32_t aH[4], aL[4];
                LDSM4(aH[0], aH[1], aH[2], aH[3], qa_off + dc * 32);
                LDSM4(aL[0], aL[1], aL[2], aL[3], qa_off + QLOD + dc * 32);
                #pragma unroll
                for (int tp = 0; tp < 8; tp++) {
                    uint32_t bK[4];
                    LDSM4(bK[0], bK[1], bK[2], bK[3], kb_off + tp * (16 * RSB) + dc * 32);
                    mma16816(S[2 * tp],     aH, bK[0], bK[1]);
                    mma16816(S[2 * tp],     aL, bK[0], bK[1]);
                    mma16816(S[2 * tp + 1], aH, bK[2], bK[3]);
                    mma16816(S[2 * tp + 1], aL, bK[2], bK[3]);
                }
            }

            // ---- softmax (no max-tracking; scores bounded) + mask ----
            const int colb = 2 * (lane & 3);
            const int kvb  = tile * 128 + colb;
            #pragma unroll
            for (int t = 0; t < 16; t++) {
                int k0 = kvb + t * 8;
                float p0 = (k0     < Lv) ? ex2f(S[t][0] * LOG2E) : 0.f;
                float p1 = (k0 + 1 < Lv) ? ex2f(S[t][1] * LOG2E) : 0.f;
                float p2 = (k0     < Lv) ? ex2f(S[t][2] * LOG2E) : 0.f;
                float p3 = (k0 + 1 < Lv) ? ex2f(S[t][3] * LOG2E) : 0.f;
                S[t][0] = p0; S[t][1] = p1; S[t][2] = p2; S[t][3] = p3;
                denA += p0 + p1;
                denB += p2 + p3;
            }

            // ---- PV: 2-term (phi + plo) x V ----
            #pragma unroll
            for (int kc = 0; kc < 8; kc++) {
                uint32_t aH[4], aL[4];
                #pragma unroll
                for (int half = 0; half < 2; half++) {
                    const float* Pt = S[2 * kc + half];
                    __half2 H0 = __floats2half2_rn(Pt[0], Pt[1]);
                    __half2 H1 = __floats2half2_rn(Pt[2], Pt[3]);
                    aH[2 * half]     = h2bits(H0);
                    aH[2 * half + 1] = h2bits(H1);
                    aL[2 * half]     = h2bits(__floats2half2_rn(Pt[0] - __low2float(H0),
                                                                Pt[1] - __high2float(H0)));
                    aL[2 * half + 1] = h2bits(__floats2half2_rn(Pt[2] - __low2float(H1),
                                                                Pt[3] - __high2float(H1)));
                }
                #pragma unroll
                for (int a = 0; a < 8; a++) {
                    uint32_t vV[4];
                    LDSM4T(vV[0], vV[1], vV[2], vV[3], vb_off + kc * (16 * RSB) + a * 32);
                    mma16816(O[2 * a],     aH, vV[0], vV[1]);
                    mma16816(O[2 * a],     aL, vV[0], vV[1]);
                    mma16816(O[2 * a + 1], aH, vV[2], vV[3]);
                    mma16816(O[2 * a + 1], aL, vV[2], vV[3]);
                }
            }
        }

        // ---- den reduce within quad rows ----
        denA += __shfl_xor_sync(0xffffffffu, denA, 1);
        denA += __shfl_xor_sync(0xffffffffu, denA, 2);
        denB += __shfl_xor_sync(0xffffffffu, denB, 1);
        denB += __shfl_xor_sync(0xffffffffu, denB, 2);

        const int rA = wrow + (lane >> 2);

        if (nc_eff == 1) {
            // single chunk: normalize + write output directly (covers Lv==0 -> zeros)
            const float invA = 1.f / fmaxf(denA, 1e-9f);
            const float invB = 1.f / fmaxf(denB, 1e-9f);
            float2* oA = (float2*)(out + outbase + (size_t)rA * DD);
            float2* oB = (float2*)(out + outbase + (size_t)(rA + 8) * DD);
            #pragma unroll
            for (int t = 0; t < 16; t++) {
                int ci = t * 4 + (lane & 3);
                oA[ci] = make_float2(O[t][0] * invA, O[t][1] * invA);
                oB[ci] = make_float2(O[t][2] * invB, O[t][3] * invB);
            }
            continue;
        }

        // ---- write raw partials ----
        {
            float* pobase = g_partO[idx];
            float2* oA = (float2*)(pobase + (size_t)rA * DD);
            float2* oB = (float2*)(pobase + (size_t)(rA + 8) * DD);
            #pragma unroll
            for (int t = 0; t < 16; t++) {
                int ci = t * 4 + (lane & 3);
                oA[ci] = make_float2(O[t][0], O[t][1]);
                oB[ci] = make_float2(O[t][2], O[t][3]);
            }
            if ((lane & 3) == 0) {
                g_partDen[idx][rA]     = denA;
                g_partDen[idx][rA + 8] = denB;
            }
        }

        // ---- arrival; last CTA of this item reduces ----
        const int item9 = rowTile | (hkv << 3) | (b << 6);
        __threadfence();
        __syncthreads();
        if (tid == 0) {
            unsigned int old = atomicAdd(&g_itemCnt[item9], 1u);
            s_fix = (old == (unsigned int)(nc_eff - 1));
        }
        __syncthreads();
        if (!s_fix) continue;
        __threadfence();   // acquire side

        {
            const int row  = tid >> 1;       // 0..63
            const int half = tid & 1;
            const unsigned int slot0 = idx & ~0x38u;

            float4 acc[16];
            #pragma unroll
            for (int j = 0; j < 16; j++) acc[j] = make_float4(0.f, 0.f, 0.f, 0.f);
            float den = 0.f;

            for (int c = 0; c < nc_eff; c++) {
                const unsigned int slot = slot0 | ((unsigned int)c << 3);
                den += g_partDen[slot][row];
                const float4* src = (const float4*)(g_partO[slot] + (size_t)row * DD + half * 64);
                #pragma unroll
                for (int j = 0; j < 16; j++) {
                    float4 s = src[j];
                    acc[j].x += s.x; acc[j].y += s.y; acc[j].z += s.z; acc[j].w += s.w;
                }
            }
            const float inv = 1.f / fmaxf(den, 1e-9f);
            float4* dst = (float4*)(out + outbase + (size_t)row * DD + half * 64);
            #pragma unroll
            for (int j = 0; j < 16; j++)
                dst[j] = make_float4(acc[j].x * inv, acc[j].y * inv, acc[j].z * inv, acc[j].w * inv);

            if (tid == 0) g_itemCnt[item9] = 0u;   // reset for next replay
        }
    }

    // ---- counter reset for next graph replay: last CTA to exit ----
    if (tid == 0) {
        unsigned int old = atomicAdd(&g_exit, 1u);
        if (old == GRID1 - 1) { g_ctr = 0u; g_exit = 0u; }
    }
}

extern "C" void kernel_launch(void* const* d_in, const int* in_sizes, int n_in,
                              void* d_out, int out_size)
{
    const float* q   = (const float*)d_in[0];
    const float* sk  = (const float*)d_in[1];
    const float* sv  = (const float*)d_in[2];
    const int*   bt  = (const int*)d_in[3];
    const int*   ctx = (const int*)d_in[4];
    float*       out = (float*)d_out;

    cudaFuncSetAttribute(attn_fused, cudaFuncAttributeMaxDynamicSharedMemorySize, SMEM_BYTES);

    attn_fused<<<GRID1, NTHREADS, SMEM_BYTES>>>(q, sk, sv, bt, ctx, out);
}